// round 12
// baseline (speedup 1.0000x reference)
#include <cuda_runtime.h>
#include <cstdint>

// ChamferLoss: B=4, C=3, N=M=8192
// loss = 2/B * sum_{b,n} max( min_m ||q_bn - r_bm||^2 , 0 )
//
// Refs split into 8 eighths (16KB smem/CTA -> up to 4 CTAs/SM, <=64 regs).
// 512 queries/block (2 per thread) vs one 1024-pt ref eighth.
// f32x2 packed FMAs (2 ref pts / instr); simple unroll-4 body, loads batched.
// Per-query unclamped partials -> g_min[eighth][]; last block finalizes.

#define BATCH     4
#define NPTS      8192
#define NSPLIT    8
#define NEIGHTH   (NPTS / NSPLIT)     // 1024 ref points per block
#define NPAIRS_B  (NEIGHTH / 2)       // 512 pairs per block
#define TPB       256
#define QPT       2
#define QPB       (TPB * QPT)         // 512 queries per block
#define QBLOCKS   (NPTS / QPB)        // 16
#define NBLOCKS   (BATCH * QBLOCKS * NSPLIT)  // 512
#define SMEM_BYTES (NPAIRS_B * 32)    // 16 KB
#define BN        (BATCH * NPTS)      // 32768

__device__ float g_min[NSPLIT * BN];
__device__ int   g_count = 0;

__device__ __forceinline__ uint64_t pk2(float lo, float hi) {
    uint64_t r;
    asm("mov.b64 %0, {%1, %2};" : "=l"(r) : "f"(lo), "f"(hi));
    return r;
}
__device__ __forceinline__ uint64_t fma_f32x2(uint64_t a, uint64_t b, uint64_t c) {
    uint64_t d;
    asm("fma.rn.f32x2 %0, %1, %2, %3;" : "=l"(d) : "l"(a), "l"(b), "l"(c));
    return d;
}
__device__ __forceinline__ float2 upk2(uint64_t v) {
    float2 r;
    asm("mov.b64 {%0, %1}, %2;" : "=f"(r.x), "=f"(r.y) : "l"(v));
    return r;
}

__global__ void __launch_bounds__(TPB, 4)
chamfer_kernel(const float* __restrict__ pc2,
               const float* __restrict__ pc1w,
               float* __restrict__ out)
{
    extern __shared__ float4 s[];  // [2*NPAIRS_B]

    // blockIdx.x = ((b*QBLOCKS)+qb)*NSPLIT + se
    const int se = blockIdx.x & (NSPLIT - 1);
    const int bq = blockIdx.x >> 3;
    const int b  = bq / QBLOCKS;
    const int qb = bq % QBLOCKS;

    // Stage this eighth's refs, pre-scaled (-2x,-2y,-2z,|r|^2), pair-packed.
    const float* __restrict__ rp = pc1w + (size_t)b * 3 * NPTS + se * NEIGHTH;
    for (int p = threadIdx.x; p < NPAIRS_B; p += TPB) {
        float x0 = rp[2 * p],            x1 = rp[2 * p + 1];
        float y0 = rp[NPTS + 2 * p],     y1 = rp[NPTS + 2 * p + 1];
        float z0 = rp[2 * NPTS + 2 * p], z1 = rp[2 * NPTS + 2 * p + 1];
        float w0 = fmaf(x0, x0, fmaf(y0, y0, z0 * z0));
        float w1 = fmaf(x1, x1, fmaf(y1, y1, z1 * z1));
        s[2 * p]     = make_float4(-2.0f * x0, -2.0f * x1, -2.0f * y0, -2.0f * y1);
        s[2 * p + 1] = make_float4(-2.0f * z0, -2.0f * z1, w0, w1);
    }
    __syncthreads();

    // Two query points per thread.
    const int na = qb * QPB + threadIdx.x;
    const int nb = na + TPB;
    const float* __restrict__ qp = pc2 + (size_t)b * 3 * NPTS;
    const float qxa = qp[na], qya = qp[NPTS + na], qza = qp[2 * NPTS + na];
    const float qxb = qp[nb], qyb = qp[NPTS + nb], qzb = qp[2 * NPTS + nb];
    const float q2a = fmaf(qxa, qxa, fmaf(qya, qya, qza * qza));
    const float q2b = fmaf(qxb, qxb, fmaf(qyb, qyb, qzb * qzb));

    const uint64_t QXA = pk2(qxa, qxa), QYA = pk2(qya, qya), QZA = pk2(qza, qza);
    const uint64_t QXB = pk2(qxb, qxb), QYB = pk2(qyb, qyb), QZB = pk2(qzb, qzb);

    float ma0 = 3.4e38f, ma1 = 3.4e38f;
    float mb0 = 3.4e38f, mb1 = 3.4e38f;

    const char* sb = (const char*)s;

    #pragma unroll 1
    for (int off = 0; off < NPAIRS_B * 32; off += 4 * 32) {
        uint64_t X[4], Y[4], Z[4], W[4];
        // Batch all 8 LDS.128 up front (MLP), then compute.
        #pragma unroll
        for (int u = 0; u < 4; u++) {
            ulonglong2 a = *(const ulonglong2*)(sb + off + u * 32);
            ulonglong2 c = *(const ulonglong2*)(sb + off + u * 32 + 16);
            X[u] = a.x; Y[u] = a.y; Z[u] = c.x; W[u] = c.y;
        }
        #pragma unroll
        for (int u = 0; u < 4; u++) {
            uint64_t ta = fma_f32x2(QXA, X[u],
                           fma_f32x2(QYA, Y[u],
                            fma_f32x2(QZA, Z[u], W[u])));
            uint64_t tb = fma_f32x2(QXB, X[u],
                           fma_f32x2(QYB, Y[u],
                            fma_f32x2(QZB, Z[u], W[u])));
            float2 fa = upk2(ta);
            float2 fb = upk2(tb);
            ma0 = fminf(ma0, fa.x);
            ma1 = fminf(ma1, fa.y);
            mb0 = fminf(mb0, fb.x);
            mb1 = fminf(mb1, fb.y);
        }
    }

    // Per-query unclamped partial for this eighth.
    float* dst = g_min + se * BN + b * NPTS;
    dst[na] = q2a + fminf(ma0, ma1);
    dst[nb] = q2b + fminf(mb0, mb1);

    // ---- last-block finalize ----
    __shared__ int is_last;
    __threadfence();
    __syncthreads();
    if (threadIdx.x == 0) {
        int old = atomicAdd(&g_count, 1);
        is_last = (old == NBLOCKS - 1);
    }
    __syncthreads();

    if (is_last) {
        __threadfence();
        float acc = 0.0f;
        // Fixed per-thread order -> deterministic final sum.
        for (int i = threadIdx.x; i < BN / 4; i += TPB) {
            const float4* g = (const float4*)g_min;
            float4 v0 = g[i];
            float4 v1 = g[(BN / 4) + i];
            float4 v2 = g[2 * (BN / 4) + i];
            float4 v3 = g[3 * (BN / 4) + i];
            float4 v4 = g[4 * (BN / 4) + i];
            float4 v5 = g[5 * (BN / 4) + i];
            float4 v6 = g[6 * (BN / 4) + i];
            float4 v7 = g[7 * (BN / 4) + i];
            float mx = fminf(fminf(fminf(v0.x, v1.x), fminf(v2.x, v3.x)),
                             fminf(fminf(v4.x, v5.x), fminf(v6.x, v7.x)));
            float my = fminf(fminf(fminf(v0.y, v1.y), fminf(v2.y, v3.y)),
                             fminf(fminf(v4.y, v5.y), fminf(v6.y, v7.y)));
            float mz = fminf(fminf(fminf(v0.z, v1.z), fminf(v2.z, v3.z)),
                             fminf(fminf(v4.z, v5.z), fminf(v6.z, v7.z)));
            float mw = fminf(fminf(fminf(v0.w, v1.w), fminf(v2.w, v3.w)),
                             fminf(fminf(v4.w, v5.w), fminf(v6.w, v7.w)));
            acc += fmaxf(mx, 0.0f) + fmaxf(my, 0.0f)
                 + fmaxf(mz, 0.0f) + fmaxf(mw, 0.0f);
        }
        __shared__ float red[TPB];
        red[threadIdx.x] = acc;
        __syncthreads();
        #pragma unroll
        for (int sH = TPB / 2; sH > 0; sH >>= 1) {
            if (threadIdx.x < sH) red[threadIdx.x] += red[threadIdx.x + sH];
            __syncthreads();
        }
        if (threadIdx.x == 0) {
            out[0] = red[0] * (2.0f / (float)BATCH);  // 2 * mean over batches
            g_count = 0;                               // reset for next replay
        }
    }
}

extern "C" void kernel_launch(void* const* d_in, const int* in_sizes, int n_in,
                              void* d_out, int out_size)
{
    const float* pc2  = (const float*)d_in[0];
    const float* pc1w = (const float*)d_in[1];
    float* out = (float*)d_out;

    cudaFuncSetAttribute(chamfer_kernel,
                         cudaFuncAttributeMaxDynamicSharedMemorySize,
                         SMEM_BYTES);

    chamfer_kernel<<<NBLOCKS, TPB, SMEM_BYTES>>>(pc2, pc1w, out);
}

// round 16
// speedup vs baseline: 1.1590x; 1.1590x over previous
#include <cuda_runtime.h>
#include <cstdint>

// ChamferLoss: B=4, C=3, N=M=8192
// loss = 2/B * sum_{b,n} max( min_m ||q_bn - r_bm||^2 , 0 )
//
// 16-way ref split (512 pts, 8KB static smem, 3 CTAs/SM).
// 1024 queries/block (4 per thread) vs one 512-pt ref slice.
// f32x2 packed FMAs; each LDS.128 pair feeds 4 query chains.
// Per-query clamped minima merged via atomicMin on uint bits (exact,
// order-independent); last block sums 32768 floats (fixed order) and scales.

#define BATCH     4
#define NPTS      8192
#define NSPLIT    16
#define SPTS      (NPTS / NSPLIT)     // 512 ref points per block
#define NPAIRS_B  (SPTS / 2)          // 256 pairs per block
#define TPB       256
#define QPT       4
#define QPB       (TPB * QPT)         // 1024 queries per block
#define QBLOCKS   (NPTS / QPB)        // 8
#define NBLOCKS   (BATCH * QBLOCKS * NSPLIT)  // 512
#define BN        (BATCH * NPTS)      // 32768

__device__ unsigned g_minbits[BN];
__device__ int      g_count = 0;

__device__ __forceinline__ uint64_t pk2(float lo, float hi) {
    uint64_t r;
    asm("mov.b64 %0, {%1, %2};" : "=l"(r) : "f"(lo), "f"(hi));
    return r;
}
__device__ __forceinline__ uint64_t fma_f32x2(uint64_t a, uint64_t b, uint64_t c) {
    uint64_t d;
    asm("fma.rn.f32x2 %0, %1, %2, %3;" : "=l"(d) : "l"(a), "l"(b), "l"(c));
    return d;
}
__device__ __forceinline__ float2 upk2(uint64_t v) {
    float2 r;
    asm("mov.b64 {%0, %1}, %2;" : "=f"(r.x), "=f"(r.y) : "l"(v));
    return r;
}

__global__ void chamfer_init_kernel()
{
    int i = blockIdx.x * blockDim.x + threadIdx.x;
    if (i < BN) g_minbits[i] = 0x7F800000u;  // +inf
}

__global__ void __launch_bounds__(TPB, 3)
chamfer_kernel(const float* __restrict__ pc2,
               const float* __restrict__ pc1w,
               float* __restrict__ out)
{
    __shared__ float4 s[2 * NPAIRS_B];   // 8 KB static

    // blockIdx.x = ((b*QBLOCKS)+qb)*NSPLIT + se
    const int se = blockIdx.x & (NSPLIT - 1);
    const int bq = blockIdx.x >> 4;
    const int b  = bq / QBLOCKS;
    const int qb = bq % QBLOCKS;

    // Stage this slice's refs, pre-scaled (-2x,-2y,-2z,|r|^2), pair-packed.
    // NPAIRS_B == TPB: exactly one pair per thread.
    {
        const float* __restrict__ rp = pc1w + (size_t)b * 3 * NPTS + se * SPTS;
        int p = threadIdx.x;
        float x0 = rp[2 * p],            x1 = rp[2 * p + 1];
        float y0 = rp[NPTS + 2 * p],     y1 = rp[NPTS + 2 * p + 1];
        float z0 = rp[2 * NPTS + 2 * p], z1 = rp[2 * NPTS + 2 * p + 1];
        float w0 = fmaf(x0, x0, fmaf(y0, y0, z0 * z0));
        float w1 = fmaf(x1, x1, fmaf(y1, y1, z1 * z1));
        s[2 * p]     = make_float4(-2.0f * x0, -2.0f * x1, -2.0f * y0, -2.0f * y1);
        s[2 * p + 1] = make_float4(-2.0f * z0, -2.0f * z1, w0, w1);
    }
    __syncthreads();

    // Four query points per thread.
    const int na = qb * QPB + threadIdx.x;
    const int nb = na + TPB;
    const int nc = na + 2 * TPB;
    const int nd = na + 3 * TPB;
    const float* __restrict__ qp = pc2 + (size_t)b * 3 * NPTS;
    const float qxa = qp[na], qya = qp[NPTS + na], qza = qp[2 * NPTS + na];
    const float qxb = qp[nb], qyb = qp[NPTS + nb], qzb = qp[2 * NPTS + nb];
    const float qxc = qp[nc], qyc = qp[NPTS + nc], qzc = qp[2 * NPTS + nc];
    const float qxd = qp[nd], qyd = qp[NPTS + nd], qzd = qp[2 * NPTS + nd];
    const float q2a = fmaf(qxa, qxa, fmaf(qya, qya, qza * qza));
    const float q2b = fmaf(qxb, qxb, fmaf(qyb, qyb, qzb * qzb));
    const float q2c = fmaf(qxc, qxc, fmaf(qyc, qyc, qzc * qzc));
    const float q2d = fmaf(qxd, qxd, fmaf(qyd, qyd, qzd * qzd));

    const uint64_t QXA = pk2(qxa, qxa), QYA = pk2(qya, qya), QZA = pk2(qza, qza);
    const uint64_t QXB = pk2(qxb, qxb), QYB = pk2(qyb, qyb), QZB = pk2(qzb, qzb);
    const uint64_t QXC = pk2(qxc, qxc), QYC = pk2(qyc, qyc), QZC = pk2(qzc, qzc);
    const uint64_t QXD = pk2(qxd, qxd), QYD = pk2(qyd, qyd), QZD = pk2(qzd, qzd);

    float ma0 = 3.4e38f, ma1 = 3.4e38f;
    float mb0 = 3.4e38f, mb1 = 3.4e38f;
    float mc0 = 3.4e38f, mc1 = 3.4e38f;
    float md0 = 3.4e38f, md1 = 3.4e38f;

    const char* sb = (const char*)s;

    #pragma unroll 1
    for (int off = 0; off < NPAIRS_B * 32; off += 2 * 32) {
        uint64_t X[2], Y[2], Z[2], W[2];
        #pragma unroll
        for (int u = 0; u < 2; u++) {
            ulonglong2 a = *(const ulonglong2*)(sb + off + u * 32);
            ulonglong2 c = *(const ulonglong2*)(sb + off + u * 32 + 16);
            X[u] = a.x; Y[u] = a.y; Z[u] = c.x; W[u] = c.y;
        }
        #pragma unroll
        for (int u = 0; u < 2; u++) {
            uint64_t za = fma_f32x2(QZA, Z[u], W[u]);
            uint64_t zb = fma_f32x2(QZB, Z[u], W[u]);
            uint64_t zc = fma_f32x2(QZC, Z[u], W[u]);
            uint64_t zd = fma_f32x2(QZD, Z[u], W[u]);
            uint64_t ta = fma_f32x2(QXA, X[u], fma_f32x2(QYA, Y[u], za));
            uint64_t tb = fma_f32x2(QXB, X[u], fma_f32x2(QYB, Y[u], zb));
            uint64_t tc = fma_f32x2(QXC, X[u], fma_f32x2(QYC, Y[u], zc));
            uint64_t td = fma_f32x2(QXD, X[u], fma_f32x2(QYD, Y[u], zd));
            float2 fa = upk2(ta), fb = upk2(tb), fc = upk2(tc), fd = upk2(td);
            ma0 = fminf(ma0, fa.x);  ma1 = fminf(ma1, fa.y);
            mb0 = fminf(mb0, fb.x);  mb1 = fminf(mb1, fb.y);
            mc0 = fminf(mc0, fc.x);  mc1 = fminf(mc1, fc.y);
            md0 = fminf(md0, fd.x);  md1 = fminf(md1, fd.y);
        }
    }

    // Clamped per-query partial; merge via atomicMin on uint bits
    // (non-negative floats are monotone in uint bit order -> exact min).
    const int base = b * NPTS;
    float va = fmaxf(q2a + fminf(ma0, ma1), 0.0f);
    float vb = fmaxf(q2b + fminf(mb0, mb1), 0.0f);
    float vc = fmaxf(q2c + fminf(mc0, mc1), 0.0f);
    float vd = fmaxf(q2d + fminf(md0, md1), 0.0f);
    atomicMin(&g_minbits[base + na], __float_as_uint(va));
    atomicMin(&g_minbits[base + nb], __float_as_uint(vb));
    atomicMin(&g_minbits[base + nc], __float_as_uint(vc));
    atomicMin(&g_minbits[base + nd], __float_as_uint(vd));

    // ---- last-block finalize (reads only 128 KB) ----
    __shared__ int is_last;
    __threadfence();
    __syncthreads();
    if (threadIdx.x == 0) {
        int old = atomicAdd(&g_count, 1);
        is_last = (old == NBLOCKS - 1);
    }
    __syncthreads();

    if (is_last) {
        __threadfence();
        const uint4* g = (const uint4*)g_minbits;
        float acc = 0.0f;
        // Fixed per-thread order -> deterministic final sum.
        for (int i = threadIdx.x; i < BN / 4; i += TPB) {
            uint4 v = g[i];
            acc += __uint_as_float(v.x) + __uint_as_float(v.y)
                 + __uint_as_float(v.z) + __uint_as_float(v.w);
        }
        __shared__ float red[TPB];
        red[threadIdx.x] = acc;
        __syncthreads();
        #pragma unroll
        for (int sH = TPB / 2; sH > 0; sH >>= 1) {
            if (threadIdx.x < sH) red[threadIdx.x] += red[threadIdx.x + sH];
            __syncthreads();
        }
        if (threadIdx.x == 0) {
            out[0] = red[0] * (2.0f / (float)BATCH);  // 2 * mean over batches
            g_count = 0;                               // reset for next replay
        }
    }
}

extern "C" void kernel_launch(void* const* d_in, const int* in_sizes, int n_in,
                              void* d_out, int out_size)
{
    const float* pc2  = (const float*)d_in[0];
    const float* pc1w = (const float*)d_in[1];
    float* out = (float*)d_out;

    chamfer_init_kernel<<<BN / 256, 256>>>();
    chamfer_kernel<<<NBLOCKS, TPB>>>(pc2, pc1w, out);
}